// round 12
// baseline (speedup 1.0000x reference)
#include <cuda_runtime.h>
#include <cuda_fp16.h>
#include <math.h>
#include <stdint.h>

#define QN 4096
#define LN 1024
#define BN 2
#define TOPK 128

// ---------------- scratch (device globals; no allocation) ----------------
__device__ __half g_kh[BN*LN*128];
__device__ __half g_vh[BN*LN*128];
__device__ float g_q[QN*128];
__device__ float g_h0[QN*256];
__device__ float g_h1[QN*256];
__device__ float g_o[BN*QN*128];
__device__ float g_mod[BN*QN*256];
__device__ float g_m0[BN*QN*256];
__device__ float g_m1[BN*QN*256];
__device__ float g_hv1[BN*QN*256];

// ------- double-buffered smem GEMM, N=256 split into 2 col-blocks -------
// Block: ROWS x 128 cols, 256 threads. Thread: (ROWS/8) rows x 4 cols.
// Inner loop is pure LDS+FFMA; global loads prefetched one chunk ahead.
// MODE 0: kv split -> OUT=K (fp16), OUT2=V (fp16), no bias
// MODE 1: OUT = X@W + b
// MODE 2: OUT = relu(hadd[row&4095] + X@W + b)
// MODE 3: OUT = relu((X+X2)@W + b)
template<int KDIM, int ROWS, int MODE>
__global__ __launch_bounds__(256) void k_gemm(const float* __restrict__ X,
                                              const float* __restrict__ X2,
                                              const float* __restrict__ W,
                                              const float* __restrict__ bias,
                                              const float* __restrict__ hadd,
                                              float* __restrict__ OUT,
                                              float* __restrict__ OUT2) {
    const int RPT = ROWS / 8;            // rows per thread
    const int NCH = KDIM / 16;           // 16-k chunks
    __shared__ float As[2][16][ROWS];    // [k][row] transposed
    __shared__ float Bs[2][16][128];
    int tid = threadIdx.x;
    int cb = blockIdx.x & 1;
    int r0 = (blockIdx.x >> 1) * ROWS;
    int ty = tid >> 5;                   // 8 row groups
    int tx = tid & 31;                   // 32 col groups of 4
    int cg = cb * 128 + tx * 4;

    // A-load assignment: ROWS*4 float4s total
    bool a_act; int a_row, a_kg;
    if (ROWS == 64) { a_act = true;      a_row = tid & 63; a_kg = tid >> 6; }
    else            { a_act = tid < 128; a_row = tid & 31; a_kg = tid >> 5; }
    // B-load assignment: 2048 floats = 8 per thread
    int b_k = tid >> 4, b_c = (tid & 15) * 8;

    float acc[RPT][4];
#pragma unroll
    for (int r = 0; r < RPT; r++)
#pragma unroll
        for (int j = 0; j < 4; j++) acc[r][j] = 0.f;

    // prefetch chunk 0
    float4 apre = make_float4(0.f, 0.f, 0.f, 0.f);
    float4 bpre0, bpre1;
    if (a_act) {
        apre = *reinterpret_cast<const float4*>(
            X + (long long)(r0 + a_row) * KDIM + a_kg * 4);
        if (MODE == 3) {
            float4 v2 = *reinterpret_cast<const float4*>(
                X2 + (long long)(r0 + a_row) * KDIM + a_kg * 4);
            apre.x += v2.x; apre.y += v2.y; apre.z += v2.z; apre.w += v2.w;
        }
    }
    bpre0 = *reinterpret_cast<const float4*>(W + (long long)b_k * 256 + cb * 128 + b_c);
    bpre1 = *reinterpret_cast<const float4*>(W + (long long)b_k * 256 + cb * 128 + b_c + 4);

    for (int c = 0; c < NCH; c++) {
        int buf = c & 1;
        // store staged regs
        if (a_act) {
            As[buf][a_kg * 4 + 0][a_row] = apre.x;
            As[buf][a_kg * 4 + 1][a_row] = apre.y;
            As[buf][a_kg * 4 + 2][a_row] = apre.z;
            As[buf][a_kg * 4 + 3][a_row] = apre.w;
        }
        *reinterpret_cast<float4*>(&Bs[buf][b_k][b_c])     = bpre0;
        *reinterpret_cast<float4*>(&Bs[buf][b_k][b_c + 4]) = bpre1;
        __syncthreads();
        // prefetch chunk c+1
        if (c + 1 < NCH) {
            int kc = (c + 1) * 16;
            if (a_act) {
                apre = *reinterpret_cast<const float4*>(
                    X + (long long)(r0 + a_row) * KDIM + kc + a_kg * 4);
                if (MODE == 3) {
                    float4 v2 = *reinterpret_cast<const float4*>(
                        X2 + (long long)(r0 + a_row) * KDIM + kc + a_kg * 4);
                    apre.x += v2.x; apre.y += v2.y; apre.z += v2.z; apre.w += v2.w;
                }
            }
            bpre0 = *reinterpret_cast<const float4*>(
                W + (long long)(kc + b_k) * 256 + cb * 128 + b_c);
            bpre1 = *reinterpret_cast<const float4*>(
                W + (long long)(kc + b_k) * 256 + cb * 128 + b_c + 4);
        }
        // compute 16 k-steps from smem
#pragma unroll
        for (int k = 0; k < 16; k++) {
            float4 b4 = *reinterpret_cast<const float4*>(&Bs[buf][k][tx * 4]);
            float ar[RPT];
            if (RPT == 8) {
                float4 t0 = *reinterpret_cast<const float4*>(&As[buf][k][ty * 8]);
                float4 t1 = *reinterpret_cast<const float4*>(&As[buf][k][ty * 8 + 4]);
                ar[0] = t0.x; ar[1] = t0.y; ar[2] = t0.z; ar[3] = t0.w;
                ar[4] = t1.x; ar[5] = t1.y; ar[6] = t1.z; ar[7] = t1.w;
            } else {
                float4 t0 = *reinterpret_cast<const float4*>(&As[buf][k][ty * RPT]);
                ar[0] = t0.x; ar[1] = t0.y; ar[2] = t0.z; ar[3] = t0.w;
            }
#pragma unroll
            for (int r = 0; r < RPT; r++) {
                acc[r][0] = fmaf(ar[r], b4.x, acc[r][0]);
                acc[r][1] = fmaf(ar[r], b4.y, acc[r][1]);
                acc[r][2] = fmaf(ar[r], b4.z, acc[r][2]);
                acc[r][3] = fmaf(ar[r], b4.w, acc[r][3]);
            }
        }
        __syncthreads();
    }

    float4 bb = make_float4(0.f, 0.f, 0.f, 0.f);
    if (MODE != 0) bb = *reinterpret_cast<const float4*>(bias + cg);
#pragma unroll
    for (int r = 0; r < RPT; r++) {
        int row = r0 + ty * RPT + r;
        float4 v;
        v.x = acc[r][0] + bb.x; v.y = acc[r][1] + bb.y;
        v.z = acc[r][2] + bb.z; v.w = acc[r][3] + bb.w;
        if (MODE == 2) {
            const float4 h4 = *reinterpret_cast<const float4*>(
                hadd + (long long)(row & (QN - 1)) * 256 + cg);
            v.x += h4.x; v.y += h4.y; v.z += h4.z; v.w += h4.w;
        }
        if (MODE >= 2) {
            v.x = fmaxf(v.x, 0.f); v.y = fmaxf(v.y, 0.f);
            v.z = fmaxf(v.z, 0.f); v.w = fmaxf(v.w, 0.f);
        }
        if (MODE == 0) {
            // K (cb==0) and V (cb==1) both stored fp16
            __half2 p0 = __floats2half2_rn(v.x, v.y);
            __half2 p1 = __floats2half2_rn(v.z, v.w);
            uint2 u;
            u.x = *reinterpret_cast<unsigned*>(&p0);
            u.y = *reinterpret_cast<unsigned*>(&p1);
            __half* dst = (cb == 0)
                ? reinterpret_cast<__half*>(OUT)  + (long long)row * 128 + cg
                : reinterpret_cast<__half*>(OUT2) + (long long)row * 128 + (cg - 128);
            *reinterpret_cast<uint2*>(dst) = u;
        } else {
            *reinterpret_cast<float4*>(OUT + (long long)row * 256 + cg) = v;
        }
    }
}

// ---------------- K2: gammas, x_q, q, h0, h1 per query ----------------
__global__ __launch_bounds__(256) void k_feat(const float* __restrict__ x,
                                              const float* __restrict__ query_W,
                                              const float* __restrict__ query_b,
                                              const float* __restrict__ q_W,
                                              const float* __restrict__ band_W,
                                              const float* __restrict__ band_b) {
    __shared__ float sg[16][4];
    __shared__ float om0[8], om1[8];
    __shared__ float gq[16][64];
    __shared__ float g1s[16][64];
    __shared__ float xq[16][256];
    int tid = threadIdx.x;
    int q0 = blockIdx.x * 16;
    if (tid < 8) {
        const float stop0 = (float)2.1072099696478683;   // log10(128)
        float e0 = 1.0f + (float)tid * ((stop0 - 1.0f) / 7.0f);
        om0[tid] = (float)exp10((double)e0);
        const float stop1 = (float)1.5051499783199061;   // log10(32)
        float e1 = 1.0f + (float)tid * ((stop1 - 1.0f) / 7.0f);
        om1[tid] = (float)exp10((double)e1);
    }
    if (tid < 64) sg[tid >> 2][tid & 3] = x[(q0 + (tid >> 2)) * 4 + (tid & 3)];
    __syncthreads();
    for (int i = tid; i < 16 * 64; i += 256) {
        int r = i >> 6, f = i & 63;
        int d = f >> 4, j = f & 15;
        float pg = (float)M_PI * sg[r][d];
        int jj = (j < 8) ? j : j - 8;
        float a0 = pg * om0[jj];
        float a1 = pg * om1[jj];
        gq[r][f]  = (j < 8) ? sinf(a0) : cosf(a0);
        g1s[r][f] = (j < 8) ? sinf(a1) : cosf(a1);
    }
    __syncthreads();
    float accx[16], acc0[16], acc1[16];
#pragma unroll
    for (int r = 0; r < 16; r++) { accx[r] = 0.f; acc0[r] = 0.f; acc1[r] = 0.f; }
    for (int f = 0; f < 64; f++) {
        float wq = query_W[f * 256 + tid];
        float w0 = band_W[f * 256 + tid];
        float w1 = band_W[64 * 256 + f * 256 + tid];
#pragma unroll
        for (int r = 0; r < 16; r++) {
            float gv = gq[r][f];
            accx[r] = fmaf(gv, wq, accx[r]);
            acc0[r] = fmaf(gv, w0, acc0[r]);
            acc1[r] = fmaf(g1s[r][f], w1, acc1[r]);
        }
    }
    float qb = query_b[tid], b0 = band_b[tid], b1 = band_b[256 + tid];
#pragma unroll
    for (int r = 0; r < 16; r++) {
        float xv = fmaxf(accx[r] + qb, 0.f);
        xq[r][tid] = xv;
        g_h0[(q0 + r) * 256 + tid] = fmaxf(acc0[r] + b0, 0.f);
        g_h1[(q0 + r) * 256 + tid] = fmaxf(acc1[r] + b1, 0.f);
    }
    __syncthreads();
    int c  = tid & 127;
    int rh = tid >> 7;
    float accq[8];
#pragma unroll
    for (int r = 0; r < 8; r++) accq[r] = 0.f;
    for (int h = 0; h < 256; h++) {
        float w = q_W[h * 128 + c];
#pragma unroll
        for (int r = 0; r < 8; r++) accq[r] = fmaf(xq[rh * 8 + r][h], w, accq[r]);
    }
#pragma unroll
    for (int r = 0; r < 8; r++) g_q[(q0 + rh * 8 + r) * 128 + c] = accq[r];
}

// ---------------- no-op: shifts k_attn into ncu's profiled slot --------
__global__ void k_nop() {}

// ---------------- K3: windowed sparse attention, block per (q, b) -------
__global__ __launch_bounds__(256) void k_attn(const float* __restrict__ x,
                                              const int* gDp, const int* gHp,
                                              const int* gWp, const int* gTp) {
    __shared__ __align__(16) float qs[128];
    __shared__ float ps[2][128];
    __shared__ float dnm[2];
    __shared__ __align__(16) float op[8][128];
    int tid = threadIdx.x;
    int q = blockIdx.x >> 1;
    int b = blockIdx.x & 1;
    if (tid < 128) qs[tid] = g_q[q * 128 + tid];

    // ---- closed-form window: 128 closest integers to u = (a2-N)/(2N) ----
    int gD = *gDp, gH = *gHp, gW = *gWp, gT = *gTp;
    float x0 = x[q * 4 + 0], x1 = x[q * 4 + 1], x2 = x[q * 4 + 2], x3 = x[q * 4 + 3];
    int zi = (int)(x0 * (float)gD);
    int yi = (int)(x1 * (float)gH);
    int xi = (int)(x2 * (float)gW);
    int ti = (int)(x3 * (float)gT);
    int idx = ((ti * gD + zi) * gH + yi) * gW + xi;
    long long Ntot = (long long)gD * gH * gW * gT;
    long long a2 = 2LL * idx * LN;
    long long num = a2 - Ntot, den = 2LL * Ntot;
    long long cl = (num >= 0) ? (num + den - 1) / den : -((-num) / den);  // ceil
    int s = (int)cl - 64;
    if (s < 0) s = 0;
    if (s > LN - TOPK) s = LN - TOPK;
    __syncthreads();

    int lane = tid & 31;
    int warp = tid >> 5;

    // sim: 8 warps x 16 keys; lane owns 4 dims (fp16 K, 8B per lane)
    {
        const __half* kb = g_kh + b * LN * 128;
        const float4 q4 = *reinterpret_cast<const float4*>(qs + lane * 4);
#pragma unroll
        for (int kk = 0; kk < 16; kk++) {
            int k = warp * 16 + kk;
            uint2 raw = *reinterpret_cast<const uint2*>(kb + (s + k) * 128 + lane * 4);
            __half2 h0 = *reinterpret_cast<__half2*>(&raw.x);
            __half2 h1 = *reinterpret_cast<__half2*>(&raw.y);
            float2 f0 = __half22float2(h0);
            float2 f1 = __half22float2(h1);
            float part = f0.x * q4.x + f0.y * q4.y + f1.x * q4.z + f1.y * q4.w;
            part += __shfl_xor_sync(0xffffffffu, part, 1);
            part += __shfl_xor_sync(0xffffffffu, part, 2);
            part += __shfl_xor_sync(0xffffffffu, part, 4);
            part += __shfl_xor_sync(0xffffffffu, part, 8);
            if ((lane & 15) == 0) ps[lane >> 4][k] = part * 0.125f;
        }
    }
    __syncthreads();
    // softmax (warp 0 -> head 0, warp 1 -> head 1)
    if (tid < 64) {
        int h = warp;
        float v[4];
        float mx = -3.4e38f;
#pragma unroll
        for (int j2 = 0; j2 < 4; j2++) { v[j2] = ps[h][lane + 32 * j2]; mx = fmaxf(mx, v[j2]); }
#pragma unroll
        for (int o2 = 16; o2 > 0; o2 >>= 1) mx = fmaxf(mx, __shfl_xor_sync(0xffffffffu, mx, o2));
        float sum = 0.f;
#pragma unroll
        for (int j2 = 0; j2 < 4; j2++) {
            float ev = expf(v[j2] - mx);
            ps[h][lane + 32 * j2] = ev;
            sum += ev;
        }
#pragma unroll
        for (int o2 = 16; o2 > 0; o2 >>= 1) sum += __shfl_xor_sync(0xffffffffu, sum, o2);
        if (lane == 0) dnm[h] = sum;
    }
    __syncthreads();
    // o: 8 key-groups x (32 lanes x 4 dims), fp16 V reads (8B per key)
    {
        int j4 = (tid & 31) * 4;          // dim quad
        int kg = tid >> 5;                // key group: 16 keys
        int h = j4 >> 6;                  // head for these dims
        const __half* vb = g_vh + b * LN * 128;
        float4 acc = make_float4(0.f, 0.f, 0.f, 0.f);
#pragma unroll
        for (int kk = 0; kk < 16; kk++) {
            int k = kg * 16 + kk;
            float p = ps[h][k];
            uint2 raw = *reinterpret_cast<const uint2*>(vb + (s + k) * 128 + j4);
            __half2 h0 = *reinterpret_cast<__half2*>(&raw.x);
            __half2 h1 = *reinterpret_cast<__half2*>(&raw.y);
            float2 f0 = __half22float2(h0);
            float2 f1 = __half22float2(h1);
            acc.x = fmaf(p, f0.x, acc.x);
            acc.y = fmaf(p, f0.y, acc.y);
            acc.z = fmaf(p, f1.x, acc.z);
            acc.w = fmaf(p, f1.y, acc.w);
        }
        *reinterpret_cast<float4*>(&op[kg][j4]) = acc;
    }
    __syncthreads();
    if (tid < 128) {
        float v = 0.f;
#pragma unroll
        for (int g = 0; g < 8; g++) v += op[g][tid];
        g_o[((long long)b * QN + q) * 128 + tid] = v / dnm[tid >> 6];
    }
}

// ---------------- K7: out = m0 . outlW0 + hv1 . outlW1 + biases ---------
__global__ __launch_bounds__(256) void k_out(const float* __restrict__ outl_W,
                                             const float* __restrict__ outl_b,
                                             float* __restrict__ out) {
    int tid = threadIdx.x;
    int r = blockIdx.x * 8 + (tid >> 5);
    int lane = tid & 31;
    float acc = 0.f;
#pragma unroll
    for (int j = 0; j < 8; j++) {
        int c = lane + 32 * j;
        acc = fmaf(g_m0[(long long)r * 256 + c],  outl_W[c],       acc);
        acc = fmaf(g_hv1[(long long)r * 256 + c], outl_W[256 + c], acc);
    }
#pragma unroll
    for (int o2 = 16; o2 > 0; o2 >>= 1) acc += __shfl_xor_sync(0xffffffffu, acc, o2);
    if (lane == 0) out[r] = acc + outl_b[0] + outl_b[1];
}

// ---------------- launch ------------------------------------------------
extern "C" void kernel_launch(void* const* d_in, const int* in_sizes, int n_in,
                              void* d_out, int out_size) {
    const float* x       = (const float*)d_in[0];
    const float* tokens  = (const float*)d_in[1];
    const float* query_W = (const float*)d_in[2];
    const float* query_b = (const float*)d_in[3];
    const float* q_W     = (const float*)d_in[4];
    const float* kv_W    = (const float*)d_in[5];
    const float* out_W   = (const float*)d_in[6];
    const float* out_b   = (const float*)d_in[7];
    const float* band_W  = (const float*)d_in[8];
    const float* band_b  = (const float*)d_in[9];
    const float* mod_W   = (const float*)d_in[10];
    const float* mod_b   = (const float*)d_in[11];
    const float* hv_W    = (const float*)d_in[12];
    const float* hv_b    = (const float*)d_in[13];
    const float* outl_W  = (const float*)d_in[14];
    const float* outl_b  = (const float*)d_in[15];
    const int*   gD      = (const int*)d_in[16];
    const int*   gH      = (const int*)d_in[17];
    const int*   gW      = (const int*)d_in[18];
    const int*   gT      = (const int*)d_in[19];
    float* out = (float*)d_out;

    float *o, *mod, *m0, *m1, *hv1, *h0, *h1;
    __half *kf, *vf;
    cudaGetSymbolAddress((void**)&kf,  g_kh);
    cudaGetSymbolAddress((void**)&vf,  g_vh);
    cudaGetSymbolAddress((void**)&o,   g_o);
    cudaGetSymbolAddress((void**)&mod, g_mod);
    cudaGetSymbolAddress((void**)&m0,  g_m0);
    cudaGetSymbolAddress((void**)&m1,  g_m1);
    cudaGetSymbolAddress((void**)&hv1, g_hv1);
    cudaGetSymbolAddress((void**)&h0,  g_h0);
    cudaGetSymbolAddress((void**)&h1,  g_h1);

    k_gemm<256,32,0><<<(BN*LN/32)*2, 256>>>(tokens, nullptr, kv_W, nullptr, nullptr, (float*)kf, (float*)vf);
    k_feat<<<QN/16, 256>>>(x, query_W, query_b, q_W, band_W, band_b);
    k_nop<<<1, 32>>>();
    k_attn<<<BN*QN, 256>>>(x, gD, gH, gW, gT);
    k_gemm<128,32,1><<<(BN*QN/32)*2, 256>>>(o,   nullptr, out_W,             out_b,       nullptr, mod, nullptr);
    k_gemm<256,32,2><<<(BN*QN/32)*2, 256>>>(mod, nullptr, mod_W,             mod_b,       h0,      m0,  nullptr);
    k_gemm<256,32,2><<<(BN*QN/32)*2, 256>>>(mod, nullptr, mod_W + 256 * 256, mod_b + 256, h1,      m1,  nullptr);
    k_gemm<256,32,3><<<(BN*QN/32)*2, 256>>>(m0,  m1,      hv_W,              hv_b,        nullptr, hv1, nullptr);
    k_out<<<BN*QN/8, 256>>>(outl_W, outl_b, out);
}

// round 13
// speedup vs baseline: 1.1706x; 1.1706x over previous
#include <cuda_runtime.h>
#include <cuda_fp16.h>
#include <math.h>
#include <stdint.h>

#define QN 4096
#define LN 1024
#define BN 2
#define TOPK 128

// ---------------- scratch (device globals; no allocation) ----------------
__device__ __half g_kh[BN*LN*128];
__device__ __half g_vh[BN*LN*128];
__device__ float g_q[QN*128];
__device__ float g_h0[QN*256];
__device__ float g_h1[QN*256];
__device__ float g_o[BN*QN*128];
__device__ float g_mod[BN*QN*256];
__device__ float g_m0[BN*QN*256];
__device__ float g_m1[BN*QN*256];
__device__ float g_hv1[BN*QN*256];

// ------- double-buffered smem GEMM, N=256 split into 2 col-blocks -------
// Block: ROWS x 128 cols, 256 threads. Thread: (ROWS/8) rows x 4 cols.
// MODE 0: kv split -> OUT=K (fp16), OUT2=V (fp16), no bias
// MODE 1: OUT = X@W + b
// MODE 2: OUT = relu(hadd[row&4095] + X@W + b)
// MODE 3: OUT = relu((X+X2)@W + b)
template<int KDIM, int ROWS, int MODE>
__global__ __launch_bounds__(256) void k_gemm(const float* __restrict__ X,
                                              const float* __restrict__ X2,
                                              const float* __restrict__ W,
                                              const float* __restrict__ bias,
                                              const float* __restrict__ hadd,
                                              float* __restrict__ OUT,
                                              float* __restrict__ OUT2) {
    const int RPT = ROWS / 8;            // rows per thread
    const int NCH = KDIM / 16;           // 16-k chunks
    __shared__ float As[2][16][ROWS];    // [k][row] transposed
    __shared__ float Bs[2][16][128];
    int tid = threadIdx.x;
    int cb = blockIdx.x & 1;
    int r0 = (blockIdx.x >> 1) * ROWS;
    int ty = tid >> 5;                   // 8 row groups
    int tx = tid & 31;                   // 32 col groups of 4
    int cg = cb * 128 + tx * 4;

    // A-load assignment: ROWS*4 float4s total
    bool a_act; int a_row, a_kg;
    if (ROWS == 64) { a_act = true;      a_row = tid & 63; a_kg = tid >> 6; }
    else            { a_act = tid < 128; a_row = tid & 31; a_kg = tid >> 5; }
    // B-load assignment: 2048 floats = 8 per thread
    int b_k = tid >> 4, b_c = (tid & 15) * 8;

    float acc[RPT][4];
#pragma unroll
    for (int r = 0; r < RPT; r++)
#pragma unroll
        for (int j = 0; j < 4; j++) acc[r][j] = 0.f;

    // prefetch chunk 0
    float4 apre = make_float4(0.f, 0.f, 0.f, 0.f);
    float4 bpre0, bpre1;
    if (a_act) {
        apre = *reinterpret_cast<const float4*>(
            X + (long long)(r0 + a_row) * KDIM + a_kg * 4);
        if (MODE == 3) {
            float4 v2 = *reinterpret_cast<const float4*>(
                X2 + (long long)(r0 + a_row) * KDIM + a_kg * 4);
            apre.x += v2.x; apre.y += v2.y; apre.z += v2.z; apre.w += v2.w;
        }
    }
    bpre0 = *reinterpret_cast<const float4*>(W + (long long)b_k * 256 + cb * 128 + b_c);
    bpre1 = *reinterpret_cast<const float4*>(W + (long long)b_k * 256 + cb * 128 + b_c + 4);

    for (int c = 0; c < NCH; c++) {
        int buf = c & 1;
        // store staged regs
        if (a_act) {
            As[buf][a_kg * 4 + 0][a_row] = apre.x;
            As[buf][a_kg * 4 + 1][a_row] = apre.y;
            As[buf][a_kg * 4 + 2][a_row] = apre.z;
            As[buf][a_kg * 4 + 3][a_row] = apre.w;
        }
        *reinterpret_cast<float4*>(&Bs[buf][b_k][b_c])     = bpre0;
        *reinterpret_cast<float4*>(&Bs[buf][b_k][b_c + 4]) = bpre1;
        __syncthreads();
        // prefetch chunk c+1
        if (c + 1 < NCH) {
            int kc = (c + 1) * 16;
            if (a_act) {
                apre = *reinterpret_cast<const float4*>(
                    X + (long long)(r0 + a_row) * KDIM + kc + a_kg * 4);
                if (MODE == 3) {
                    float4 v2 = *reinterpret_cast<const float4*>(
                        X2 + (long long)(r0 + a_row) * KDIM + kc + a_kg * 4);
                    apre.x += v2.x; apre.y += v2.y; apre.z += v2.z; apre.w += v2.w;
                }
            }
            bpre0 = *reinterpret_cast<const float4*>(
                W + (long long)(kc + b_k) * 256 + cb * 128 + b_c);
            bpre1 = *reinterpret_cast<const float4*>(
                W + (long long)(kc + b_k) * 256 + cb * 128 + b_c + 4);
        }
        // compute 16 k-steps from smem
#pragma unroll
        for (int k = 0; k < 16; k++) {
            float4 b4 = *reinterpret_cast<const float4*>(&Bs[buf][k][tx * 4]);
            float ar[RPT];
            if (RPT == 8) {
                float4 t0 = *reinterpret_cast<const float4*>(&As[buf][k][ty * 8]);
                float4 t1 = *reinterpret_cast<const float4*>(&As[buf][k][ty * 8 + 4]);
                ar[0] = t0.x; ar[1] = t0.y; ar[2] = t0.z; ar[3] = t0.w;
                ar[4] = t1.x; ar[5] = t1.y; ar[6] = t1.z; ar[7] = t1.w;
            } else {
                float4 t0 = *reinterpret_cast<const float4*>(&As[buf][k][ty * RPT]);
                ar[0] = t0.x; ar[1] = t0.y; ar[2] = t0.z; ar[3] = t0.w;
            }
#pragma unroll
            for (int r = 0; r < RPT; r++) {
                acc[r][0] = fmaf(ar[r], b4.x, acc[r][0]);
                acc[r][1] = fmaf(ar[r], b4.y, acc[r][1]);
                acc[r][2] = fmaf(ar[r], b4.z, acc[r][2]);
                acc[r][3] = fmaf(ar[r], b4.w, acc[r][3]);
            }
        }
        __syncthreads();
    }

    float4 bb = make_float4(0.f, 0.f, 0.f, 0.f);
    if (MODE != 0) bb = *reinterpret_cast<const float4*>(bias + cg);
#pragma unroll
    for (int r = 0; r < RPT; r++) {
        int row = r0 + ty * RPT + r;
        float4 v;
        v.x = acc[r][0] + bb.x; v.y = acc[r][1] + bb.y;
        v.z = acc[r][2] + bb.z; v.w = acc[r][3] + bb.w;
        if (MODE == 2) {
            const float4 h4 = *reinterpret_cast<const float4*>(
                hadd + (long long)(row & (QN - 1)) * 256 + cg);
            v.x += h4.x; v.y += h4.y; v.z += h4.z; v.w += h4.w;
        }
        if (MODE >= 2) {
            v.x = fmaxf(v.x, 0.f); v.y = fmaxf(v.y, 0.f);
            v.z = fmaxf(v.z, 0.f); v.w = fmaxf(v.w, 0.f);
        }
        if (MODE == 0) {
            // K (cb==0) and V (cb==1) both stored fp16
            __half2 p0 = __floats2half2_rn(v.x, v.y);
            __half2 p1 = __floats2half2_rn(v.z, v.w);
            uint2 u;
            u.x = *reinterpret_cast<unsigned*>(&p0);
            u.y = *reinterpret_cast<unsigned*>(&p1);
            __half* dst = (cb == 0)
                ? reinterpret_cast<__half*>(OUT)  + (long long)row * 128 + cg
                : reinterpret_cast<__half*>(OUT2) + (long long)row * 128 + (cg - 128);
            *reinterpret_cast<uint2*>(dst) = u;
        } else {
            *reinterpret_cast<float4*>(OUT + (long long)row * 256 + cg) = v;
        }
    }
}

// ---------------- K2: gammas, x_q, q, h0, h1 per query ----------------
__global__ __launch_bounds__(256) void k_feat(const float* __restrict__ x,
                                              const float* __restrict__ query_W,
                                              const float* __restrict__ query_b,
                                              const float* __restrict__ q_W,
                                              const float* __restrict__ band_W,
                                              const float* __restrict__ band_b) {
    __shared__ float sg[16][4];
    __shared__ float om0[8], om1[8];
    __shared__ float gq[16][64];
    __shared__ float g1s[16][64];
    __shared__ float xq[16][256];
    int tid = threadIdx.x;
    int q0 = blockIdx.x * 16;
    if (tid < 8) {
        const float stop0 = (float)2.1072099696478683;   // log10(128)
        float e0 = 1.0f + (float)tid * ((stop0 - 1.0f) / 7.0f);
        om0[tid] = (float)exp10((double)e0);
        const float stop1 = (float)1.5051499783199061;   // log10(32)
        float e1 = 1.0f + (float)tid * ((stop1 - 1.0f) / 7.0f);
        om1[tid] = (float)exp10((double)e1);
    }
    if (tid < 64) sg[tid >> 2][tid & 3] = x[(q0 + (tid >> 2)) * 4 + (tid & 3)];
    __syncthreads();
    for (int i = tid; i < 16 * 64; i += 256) {
        int r = i >> 6, f = i & 63;
        int d = f >> 4, j = f & 15;
        float pg = (float)M_PI * sg[r][d];
        int jj = (j < 8) ? j : j - 8;
        float a0 = pg * om0[jj];
        float a1 = pg * om1[jj];
        gq[r][f]  = (j < 8) ? sinf(a0) : cosf(a0);
        g1s[r][f] = (j < 8) ? sinf(a1) : cosf(a1);
    }
    __syncthreads();
    float accx[16], acc0[16], acc1[16];
#pragma unroll
    for (int r = 0; r < 16; r++) { accx[r] = 0.f; acc0[r] = 0.f; acc1[r] = 0.f; }
    for (int f = 0; f < 64; f++) {
        float wq = query_W[f * 256 + tid];
        float w0 = band_W[f * 256 + tid];
        float w1 = band_W[64 * 256 + f * 256 + tid];
#pragma unroll
        for (int r = 0; r < 16; r++) {
            float gv = gq[r][f];
            accx[r] = fmaf(gv, wq, accx[r]);
            acc0[r] = fmaf(gv, w0, acc0[r]);
            acc1[r] = fmaf(g1s[r][f], w1, acc1[r]);
        }
    }
    float qb = query_b[tid], b0 = band_b[tid], b1 = band_b[256 + tid];
#pragma unroll
    for (int r = 0; r < 16; r++) {
        float xv = fmaxf(accx[r] + qb, 0.f);
        xq[r][tid] = xv;
        g_h0[(q0 + r) * 256 + tid] = fmaxf(acc0[r] + b0, 0.f);
        g_h1[(q0 + r) * 256 + tid] = fmaxf(acc1[r] + b1, 0.f);
    }
    __syncthreads();
    int c  = tid & 127;
    int rh = tid >> 7;
    float accq[8];
#pragma unroll
    for (int r = 0; r < 8; r++) accq[r] = 0.f;
    for (int h = 0; h < 256; h++) {
        float w = q_W[h * 128 + c];
#pragma unroll
        for (int r = 0; r < 8; r++) accq[r] = fmaf(xq[rh * 8 + r][h], w, accq[r]);
    }
#pragma unroll
    for (int r = 0; r < 8; r++) g_q[(q0 + rh * 8 + r) * 128 + c] = accq[r];
}

// ---------------- no-op: shifts k_attn into ncu's profiled slot --------
__global__ void k_nop() {}

// ---------------- K3: windowed sparse attention, block per (q, b) -------
// sim: 2 keys per LDG.128 per warp; o: 16 half-warp groups, 16B V loads.
__global__ __launch_bounds__(256) void k_attn(const float* __restrict__ x,
                                              const int* gDp, const int* gHp,
                                              const int* gWp, const int* gTp) {
    __shared__ __align__(16) float qs[128];
    __shared__ float ps[2][128];
    __shared__ float dnm[2];
    __shared__ __align__(16) float op[16][128];
    int tid = threadIdx.x;
    int q = blockIdx.x >> 1;
    int b = blockIdx.x & 1;
    if (tid < 128) qs[tid] = g_q[q * 128 + tid];

    // ---- closed-form window: 128 closest integers to u = (a2-N)/(2N) ----
    int gD = *gDp, gH = *gHp, gW = *gWp, gT = *gTp;
    float x0 = x[q * 4 + 0], x1 = x[q * 4 + 1], x2 = x[q * 4 + 2], x3 = x[q * 4 + 3];
    int zi = (int)(x0 * (float)gD);
    int yi = (int)(x1 * (float)gH);
    int xi = (int)(x2 * (float)gW);
    int ti = (int)(x3 * (float)gT);
    int idx = ((ti * gD + zi) * gH + yi) * gW + xi;
    long long Ntot = (long long)gD * gH * gW * gT;
    long long a2 = 2LL * idx * LN;
    long long num = a2 - Ntot, den = 2LL * Ntot;
    long long cl = (num >= 0) ? (num + den - 1) / den : -((-num) / den);  // ceil
    int s = (int)cl - 64;
    if (s < 0) s = 0;
    if (s > LN - TOPK) s = LN - TOPK;
    __syncthreads();

    int lane = tid & 31;
    int warp = tid >> 5;

    // sim: each warp 16 keys, 2 keys per iteration (LDG.128 per lane)
    {
        const __half* kb = g_kh + b * LN * 128;
        int halfp = lane >> 4;            // which key of the pair
        int l16 = lane & 15;              // dim octet index (8 dims each)
        float qv[8];
        {
            float4 q0 = *reinterpret_cast<const float4*>(qs + l16 * 8);
            float4 q1 = *reinterpret_cast<const float4*>(qs + l16 * 8 + 4);
            qv[0] = q0.x; qv[1] = q0.y; qv[2] = q0.z; qv[3] = q0.w;
            qv[4] = q1.x; qv[5] = q1.y; qv[6] = q1.z; qv[7] = q1.w;
        }
#pragma unroll
        for (int it = 0; it < 8; it++) {
            int k = warp * 16 + it * 2 + halfp;
            uint4 raw = *reinterpret_cast<const uint4*>(kb + (s + k) * 128 + l16 * 8);
            __half2 h0 = *reinterpret_cast<__half2*>(&raw.x);
            __half2 h1 = *reinterpret_cast<__half2*>(&raw.y);
            __half2 h2 = *reinterpret_cast<__half2*>(&raw.z);
            __half2 h3 = *reinterpret_cast<__half2*>(&raw.w);
            float2 f0 = __half22float2(h0);
            float2 f1 = __half22float2(h1);
            float2 f2 = __half22float2(h2);
            float2 f3 = __half22float2(h3);
            float part = f0.x * qv[0] + f0.y * qv[1] + f1.x * qv[2] + f1.y * qv[3]
                       + f2.x * qv[4] + f2.y * qv[5] + f3.x * qv[6] + f3.y * qv[7];
            part += __shfl_xor_sync(0xffffffffu, part, 1);
            part += __shfl_xor_sync(0xffffffffu, part, 2);
            part += __shfl_xor_sync(0xffffffffu, part, 4);
            if ((lane & 7) == 0) ps[(lane >> 3) & 1][k] = part * 0.125f;
        }
    }
    __syncthreads();
    // softmax (warp 0 -> head 0, warp 1 -> head 1)
    if (tid < 64) {
        int h = warp;
        float v[4];
        float mx = -3.4e38f;
#pragma unroll
        for (int j2 = 0; j2 < 4; j2++) { v[j2] = ps[h][lane + 32 * j2]; mx = fmaxf(mx, v[j2]); }
#pragma unroll
        for (int o2 = 16; o2 > 0; o2 >>= 1) mx = fmaxf(mx, __shfl_xor_sync(0xffffffffu, mx, o2));
        float sum = 0.f;
#pragma unroll
        for (int j2 = 0; j2 < 4; j2++) {
            float ev = expf(v[j2] - mx);
            ps[h][lane + 32 * j2] = ev;
            sum += ev;
        }
#pragma unroll
        for (int o2 = 16; o2 > 0; o2 >>= 1) sum += __shfl_xor_sync(0xffffffffu, sum, o2);
        if (lane == 0) dnm[h] = sum;
    }
    __syncthreads();
    // o: 16 half-warp key groups x 8 keys; thread owns 8 dims (16B V loads)
    {
        int j8 = (tid & 15) * 8;          // dim octet
        int kg = tid >> 4;                // key group: 8 keys
        int h = j8 >> 6;                  // head for these dims
        const __half* vb = g_vh + b * LN * 128;
        float a[8];
#pragma unroll
        for (int i = 0; i < 8; i++) a[i] = 0.f;
#pragma unroll
        for (int kk = 0; kk < 8; kk++) {
            int k = kg * 8 + kk;
            float p = ps[h][k];
            uint4 raw = *reinterpret_cast<const uint4*>(vb + (s + k) * 128 + j8);
            __half2 h0 = *reinterpret_cast<__half2*>(&raw.x);
            __half2 h1 = *reinterpret_cast<__half2*>(&raw.y);
            __half2 h2 = *reinterpret_cast<__half2*>(&raw.z);
            __half2 h3 = *reinterpret_cast<__half2*>(&raw.w);
            float2 f0 = __half22float2(h0);
            float2 f1 = __half22float2(h1);
            float2 f2 = __half22float2(h2);
            float2 f3 = __half22float2(h3);
            a[0] = fmaf(p, f0.x, a[0]); a[1] = fmaf(p, f0.y, a[1]);
            a[2] = fmaf(p, f1.x, a[2]); a[3] = fmaf(p, f1.y, a[3]);
            a[4] = fmaf(p, f2.x, a[4]); a[5] = fmaf(p, f2.y, a[5]);
            a[6] = fmaf(p, f3.x, a[6]); a[7] = fmaf(p, f3.y, a[7]);
        }
        *reinterpret_cast<float4*>(&op[kg][j8])     = make_float4(a[0], a[1], a[2], a[3]);
        *reinterpret_cast<float4*>(&op[kg][j8 + 4]) = make_float4(a[4], a[5], a[6], a[7]);
    }
    __syncthreads();
    if (tid < 128) {
        float v = 0.f;
#pragma unroll
        for (int g = 0; g < 16; g++) v += op[g][tid];
        g_o[((long long)b * QN + q) * 128 + tid] = v / dnm[tid >> 6];
    }
}

// ---------------- K7: out = m0 . outlW0 + hv1 . outlW1 + biases ---------
__global__ __launch_bounds__(256) void k_out(const float* __restrict__ outl_W,
                                             const float* __restrict__ outl_b,
                                             float* __restrict__ out) {
    int tid = threadIdx.x;
    int r = blockIdx.x * 8 + (tid >> 5);
    int lane = tid & 31;
    float acc = 0.f;
#pragma unroll
    for (int j = 0; j < 8; j++) {
        int c = lane + 32 * j;
        acc = fmaf(g_m0[(long long)r * 256 + c],  outl_W[c],       acc);
        acc = fmaf(g_hv1[(long long)r * 256 + c], outl_W[256 + c], acc);
    }
#pragma unroll
    for (int o2 = 16; o2 > 0; o2 >>= 1) acc += __shfl_xor_sync(0xffffffffu, acc, o2);
    if (lane == 0) out[r] = acc + outl_b[0] + outl_b[1];
}

// ---------------- launch ------------------------------------------------
extern "C" void kernel_launch(void* const* d_in, const int* in_sizes, int n_in,
                              void* d_out, int out_size) {
    const float* x       = (const float*)d_in[0];
    const float* tokens  = (const float*)d_in[1];
    const float* query_W = (const float*)d_in[2];
    const float* query_b = (const float*)d_in[3];
    const float* q_W     = (const float*)d_in[4];
    const float* kv_W    = (const float*)d_in[5];
    const float* out_W   = (const float*)d_in[6];
    const float* out_b   = (const float*)d_in[7];
    const float* band_W  = (const float*)d_in[8];
    const float* band_b  = (const float*)d_in[9];
    const float* mod_W   = (const float*)d_in[10];
    const float* mod_b   = (const float*)d_in[11];
    const float* hv_W    = (const float*)d_in[12];
    const float* hv_b    = (const float*)d_in[13];
    const float* outl_W  = (const float*)d_in[14];
    const float* outl_b  = (const float*)d_in[15];
    const int*   gD      = (const int*)d_in[16];
    const int*   gH      = (const int*)d_in[17];
    const int*   gW      = (const int*)d_in[18];
    const int*   gT      = (const int*)d_in[19];
    float* out = (float*)d_out;

    float *o, *mod, *m0, *m1, *hv1, *h0, *h1;
    __half *kf, *vf;
    cudaGetSymbolAddress((void**)&kf,  g_kh);
    cudaGetSymbolAddress((void**)&vf,  g_vh);
    cudaGetSymbolAddress((void**)&o,   g_o);
    cudaGetSymbolAddress((void**)&mod, g_mod);
    cudaGetSymbolAddress((void**)&m0,  g_m0);
    cudaGetSymbolAddress((void**)&m1,  g_m1);
    cudaGetSymbolAddress((void**)&hv1, g_hv1);
    cudaGetSymbolAddress((void**)&h0,  g_h0);
    cudaGetSymbolAddress((void**)&h1,  g_h1);

    k_gemm<256,32,0><<<(BN*LN/32)*2, 256>>>(tokens, nullptr, kv_W, nullptr, nullptr, (float*)kf, (float*)vf);
    k_feat<<<QN/16, 256>>>(x, query_W, query_b, q_W, band_W, band_b);
    k_nop<<<1, 32>>>();
    k_attn<<<BN*QN, 256>>>(x, gD, gH, gW, gT);
    k_gemm<128,64,1><<<(BN*QN/64)*2, 256>>>(o,   nullptr, out_W,             out_b,       nullptr, mod, nullptr);
    k_gemm<256,64,2><<<(BN*QN/64)*2, 256>>>(mod, nullptr, mod_W,             mod_b,       h0,      m0,  nullptr);
    k_gemm<256,64,2><<<(BN*QN/64)*2, 256>>>(mod, nullptr, mod_W + 256 * 256, mod_b + 256, h1,      m1,  nullptr);
    k_gemm<256,64,3><<<(BN*QN/64)*2, 256>>>(m0,  m1,      hv_W,              hv_b,        nullptr, hv1, nullptr);
    k_out<<<BN*QN/8, 256>>>(outl_W, outl_b, out);
}

// round 15
// speedup vs baseline: 1.5578x; 1.3308x over previous
#include <cuda_runtime.h>
#include <cuda_fp16.h>
#include <math.h>
#include <stdint.h>

#define QN 4096
#define LN 1024
#define BN 2
#define TOPK 128

// ---------------- scratch (device globals; no allocation) ----------------
__device__ __half g_kh[BN*LN*128];
__device__ __half g_vh[BN*LN*128];
__device__ float g_q[QN*128];
__device__ float g_h0[QN*256];
__device__ float g_h1[QN*256];
__device__ float g_o[BN*QN*128];
__device__ float g_mod[BN*QN*256];
__device__ float g_m0[BN*QN*256];
__device__ float g_m1[BN*QN*256];
__device__ float g_hv1[BN*QN*256];
// transposed hi/lo split weights [n][k], slots:
//  s0 out_W  [256][128] @0 ; s1 mod_W0 [256][256] @32768
//  s2 mod_W1 [256][256] @98304 ; s3 hv_W [256][256] @163840
__device__ __half g_wh[229376];
__device__ __half g_wl[229376];

// ---------------- combined weight prep: transpose + fp16 hi/lo ----------
__global__ __launch_bounds__(256) void k_wprep(const float* __restrict__ out_W,
                                               const float* __restrict__ mod_W,
                                               const float* __restrict__ hv_W) {
    int e = blockIdx.x * 256 + threadIdx.x;   // 0 .. 229375
    const float* W; int base, K, N, off;
    if (e < 32768)       { W = out_W;          base = 0;      K = 128; N = 256; off = e; }
    else if (e < 98304)  { W = mod_W;          base = 32768;  K = 256; N = 256; off = e - 32768; }
    else if (e < 163840) { W = mod_W + 65536;  base = 98304;  K = 256; N = 256; off = e - 98304; }
    else                 { W = hv_W;           base = 163840; K = 256; N = 256; off = e - 163840; }
    int k = off / N, n = off % N;             // src is [K][N] row-major
    float w = W[off];
    __half hi = __float2half_rn(w);
    float lo = w - __half2float(hi);
    g_wh[base + n * K + k] = hi;
    g_wl[base + n * K + k] = __float2half_rn(lo);
}

// ---------------- mma.sync helper ---------------------------------------
__device__ __forceinline__ void mma16816(float* c, const uint32_t* a, const uint32_t* b) {
    asm("mma.sync.aligned.m16n8k16.row.col.f32.f16.f16.f32 "
        "{%0,%1,%2,%3}, {%4,%5,%6,%7}, {%8,%9}, {%0,%1,%2,%3};"
        : "+f"(c[0]), "+f"(c[1]), "+f"(c[2]), "+f"(c[3])
        : "r"(a[0]), "r"(a[1]), "r"(a[2]), "r"(a[3]), "r"(b[0]), "r"(b[1]));
}

// ---------------- tensor-core GEMM: OUT[8192 x 256] = X @ W + ... -------
// Block 64 rows x 128 cols, 8 warps (warp: 32x32 tile). fp16 hi/lo 3-term.
// MODE 1: OUT = X@W + b ; MODE 2: relu(hadd[row&4095] + X@W + b)
// MODE 3: relu((X+X2)@W + b)
template<int KDIM, int MODE>
__global__ __launch_bounds__(256) void k_tmma(const float* __restrict__ X,
                                              const float* __restrict__ X2,
                                              const __half* __restrict__ Wh,
                                              const __half* __restrict__ Wl,
                                              const float* __restrict__ bias,
                                              const float* __restrict__ hadd,
                                              float* __restrict__ OUT) {
    const int P = 40;                         // padded halves per 32-k row
    __shared__ __half Ah[64 * P], Al[64 * P];
    __shared__ __half Bh[128 * P], Bl[128 * P];
    int tid = threadIdx.x, lane = tid & 31, warp = tid >> 5;
    int nb = blockIdx.x & 1;
    int r0 = (blockIdx.x >> 1) * 64;
    int n0 = nb * 128;
    int wm = (warp & 1) * 32;                 // warp row offset in block
    int wn = (warp >> 1) * 32;                // warp col offset in 128
    int g = lane >> 2, tig = lane & 3;

    float acc[2][4][4];
#pragma unroll
    for (int m = 0; m < 2; m++)
#pragma unroll
        for (int n = 0; n < 4; n++)
#pragma unroll
            for (int j = 0; j < 4; j++) acc[m][n][j] = 0.f;

    for (int kc = 0; kc < KDIM; kc += 32) {
        // stage A: 64 rows x 32 k fp32 -> hi/lo fp16
#pragma unroll
        for (int it = 0; it < 2; it++) {
            int i = it * 256 + tid;
            int row = i >> 3, k4 = (i & 7) * 4;
            float4 v = *reinterpret_cast<const float4*>(
                X + (long long)(r0 + row) * KDIM + kc + k4);
            if (MODE == 3) {
                float4 v2 = *reinterpret_cast<const float4*>(
                    X2 + (long long)(r0 + row) * KDIM + kc + k4);
                v.x += v2.x; v.y += v2.y; v.z += v2.z; v.w += v2.w;
            }
            __half hx = __float2half_rn(v.x), hy = __float2half_rn(v.y);
            __half hz = __float2half_rn(v.z), hw = __float2half_rn(v.w);
            __half2 h01; h01.x = hx; h01.y = hy;
            __half2 h23; h23.x = hz; h23.y = hw;
            uint2 uh;
            uh.x = *reinterpret_cast<unsigned*>(&h01);
            uh.y = *reinterpret_cast<unsigned*>(&h23);
            *reinterpret_cast<uint2*>(&Ah[row * P + k4]) = uh;
            __half2 l01 = __floats2half2_rn(v.x - __half2float(hx), v.y - __half2float(hy));
            __half2 l23 = __floats2half2_rn(v.z - __half2float(hz), v.w - __half2float(hw));
            uint2 ul;
            ul.x = *reinterpret_cast<unsigned*>(&l01);
            ul.y = *reinterpret_cast<unsigned*>(&l23);
            *reinterpret_cast<uint2*>(&Al[row * P + k4]) = ul;
        }
        // stage B: Wh/Wl [n][KDIM] rows n0..n0+127, k kc..kc+31
#pragma unroll
        for (int it = 0; it < 2; it++) {
            int i = it * 256 + tid;
            int n = i >> 2, k8 = (i & 3) * 8;
            uint4 h = *reinterpret_cast<const uint4*>(Wh + (long long)(n0 + n) * KDIM + kc + k8);
            *reinterpret_cast<uint4*>(&Bh[n * P + k8]) = h;
            uint4 l = *reinterpret_cast<const uint4*>(Wl + (long long)(n0 + n) * KDIM + kc + k8);
            *reinterpret_cast<uint4*>(&Bl[n * P + k8]) = l;
        }
        __syncthreads();
#pragma unroll
        for (int ks = 0; ks < 32; ks += 16) {
            uint32_t ah[2][4], al[2][4], bh[4][2], bl[4][2];
#pragma unroll
            for (int m = 0; m < 2; m++) {
                int rb = wm + m * 16;
                ah[m][0] = *reinterpret_cast<const uint32_t*>(&Ah[(rb + g) * P + ks + 2 * tig]);
                ah[m][1] = *reinterpret_cast<const uint32_t*>(&Ah[(rb + g + 8) * P + ks + 2 * tig]);
                ah[m][2] = *reinterpret_cast<const uint32_t*>(&Ah[(rb + g) * P + ks + 2 * tig + 8]);
                ah[m][3] = *reinterpret_cast<const uint32_t*>(&Ah[(rb + g + 8) * P + ks + 2 * tig + 8]);
                al[m][0] = *reinterpret_cast<const uint32_t*>(&Al[(rb + g) * P + ks + 2 * tig]);
                al[m][1] = *reinterpret_cast<const uint32_t*>(&Al[(rb + g + 8) * P + ks + 2 * tig]);
                al[m][2] = *reinterpret_cast<const uint32_t*>(&Al[(rb + g) * P + ks + 2 * tig + 8]);
                al[m][3] = *reinterpret_cast<const uint32_t*>(&Al[(rb + g + 8) * P + ks + 2 * tig + 8]);
            }
#pragma unroll
            for (int n = 0; n < 4; n++) {
                int bn = wn + n * 8 + g;
                bh[n][0] = *reinterpret_cast<const uint32_t*>(&Bh[bn * P + ks + 2 * tig]);
                bh[n][1] = *reinterpret_cast<const uint32_t*>(&Bh[bn * P + ks + 2 * tig + 8]);
                bl[n][0] = *reinterpret_cast<const uint32_t*>(&Bl[bn * P + ks + 2 * tig]);
                bl[n][1] = *reinterpret_cast<const uint32_t*>(&Bl[bn * P + ks + 2 * tig + 8]);
            }
#pragma unroll
            for (int m = 0; m < 2; m++)
#pragma unroll
                for (int n = 0; n < 4; n++) {
                    mma16816(acc[m][n], ah[m], bh[n]);
                    mma16816(acc[m][n], ah[m], bl[n]);
                    mma16816(acc[m][n], al[m], bh[n]);
                }
        }
        __syncthreads();
    }

    // epilogue: c0,c1 = (row g, col 2tig..+1); c2,c3 = (row g+8, same cols)
#pragma unroll
    for (int m = 0; m < 2; m++)
#pragma unroll
        for (int n = 0; n < 4; n++) {
            int row = r0 + wm + m * 16 + g;
            int col = n0 + wn + n * 8 + 2 * tig;
            float2 bv = *reinterpret_cast<const float2*>(bias + col);
            float v0 = acc[m][n][0] + bv.x, v1 = acc[m][n][1] + bv.y;
            float v2 = acc[m][n][2] + bv.x, v3 = acc[m][n][3] + bv.y;
            if (MODE == 2) {
                float2 h0 = *reinterpret_cast<const float2*>(
                    hadd + (long long)(row & (QN - 1)) * 256 + col);
                float2 h1 = *reinterpret_cast<const float2*>(
                    hadd + (long long)((row + 8) & (QN - 1)) * 256 + col);
                v0 += h0.x; v1 += h0.y; v2 += h1.x; v3 += h1.y;
            }
            if (MODE >= 2) {
                v0 = fmaxf(v0, 0.f); v1 = fmaxf(v1, 0.f);
                v2 = fmaxf(v2, 0.f); v3 = fmaxf(v3, 0.f);
            }
            *reinterpret_cast<float2*>(OUT + (long long)row * 256 + col) = make_float2(v0, v1);
            *reinterpret_cast<float2*>(OUT + (long long)(row + 8) * 256 + col) = make_float2(v2, v3);
        }
}

// ------- scalar double-buffered GEMM (kv only, MODE 0) ------------------
template<int KDIM, int ROWS, int MODE>
__global__ __launch_bounds__(256) void k_gemm(const float* __restrict__ X,
                                              const float* __restrict__ X2,
                                              const float* __restrict__ W,
                                              const float* __restrict__ bias,
                                              const float* __restrict__ hadd,
                                              float* __restrict__ OUT,
                                              float* __restrict__ OUT2) {
    const int RPT = ROWS / 8;
    const int NCH = KDIM / 16;
    __shared__ float As[2][16][ROWS];
    __shared__ float Bs[2][16][128];
    int tid = threadIdx.x;
    int cb = blockIdx.x & 1;
    int r0 = (blockIdx.x >> 1) * ROWS;
    int ty = tid >> 5;
    int tx = tid & 31;
    int cg = cb * 128 + tx * 4;

    bool a_act; int a_row, a_kg;
    if (ROWS == 64) { a_act = true;      a_row = tid & 63; a_kg = tid >> 6; }
    else            { a_act = tid < 128; a_row = tid & 31; a_kg = tid >> 5; }
    int b_k = tid >> 4, b_c = (tid & 15) * 8;

    float acc[RPT][4];
#pragma unroll
    for (int r = 0; r < RPT; r++)
#pragma unroll
        for (int j = 0; j < 4; j++) acc[r][j] = 0.f;

    float4 apre = make_float4(0.f, 0.f, 0.f, 0.f);
    float4 bpre0, bpre1;
    if (a_act) {
        apre = *reinterpret_cast<const float4*>(
            X + (long long)(r0 + a_row) * KDIM + a_kg * 4);
    }
    bpre0 = *reinterpret_cast<const float4*>(W + (long long)b_k * 256 + cb * 128 + b_c);
    bpre1 = *reinterpret_cast<const float4*>(W + (long long)b_k * 256 + cb * 128 + b_c + 4);

    for (int c = 0; c < NCH; c++) {
        int buf = c & 1;
        if (a_act) {
            As[buf][a_kg * 4 + 0][a_row] = apre.x;
            As[buf][a_kg * 4 + 1][a_row] = apre.y;
            As[buf][a_kg * 4 + 2][a_row] = apre.z;
            As[buf][a_kg * 4 + 3][a_row] = apre.w;
        }
        *reinterpret_cast<float4*>(&Bs[buf][b_k][b_c])     = bpre0;
        *reinterpret_cast<float4*>(&Bs[buf][b_k][b_c + 4]) = bpre1;
        __syncthreads();
        if (c + 1 < NCH) {
            int kc = (c + 1) * 16;
            if (a_act) {
                apre = *reinterpret_cast<const float4*>(
                    X + (long long)(r0 + a_row) * KDIM + kc + a_kg * 4);
            }
            bpre0 = *reinterpret_cast<const float4*>(
                W + (long long)(kc + b_k) * 256 + cb * 128 + b_c);
            bpre1 = *reinterpret_cast<const float4*>(
                W + (long long)(kc + b_k) * 256 + cb * 128 + b_c + 4);
        }
#pragma unroll
        for (int k = 0; k < 16; k++) {
            float4 b4 = *reinterpret_cast<const float4*>(&Bs[buf][k][tx * 4]);
            float ar[RPT];
            float4 t0 = *reinterpret_cast<const float4*>(&As[buf][k][ty * RPT]);
            ar[0] = t0.x; ar[1] = t0.y; ar[2] = t0.z; ar[3] = t0.w;
#pragma unroll
            for (int r = 0; r < RPT; r++) {
                acc[r][0] = fmaf(ar[r], b4.x, acc[r][0]);
                acc[r][1] = fmaf(ar[r], b4.y, acc[r][1]);
                acc[r][2] = fmaf(ar[r], b4.z, acc[r][2]);
                acc[r][3] = fmaf(ar[r], b4.w, acc[r][3]);
            }
        }
        __syncthreads();
    }

#pragma unroll
    for (int r = 0; r < RPT; r++) {
        int row = r0 + ty * RPT + r;
        float4 v;
        v.x = acc[r][0]; v.y = acc[r][1]; v.z = acc[r][2]; v.w = acc[r][3];
        __half2 p0 = __floats2half2_rn(v.x, v.y);
        __half2 p1 = __floats2half2_rn(v.z, v.w);
        uint2 u;
        u.x = *reinterpret_cast<unsigned*>(&p0);
        u.y = *reinterpret_cast<unsigned*>(&p1);
        __half* dst = (cb == 0)
            ? reinterpret_cast<__half*>(OUT)  + (long long)row * 128 + cg
            : reinterpret_cast<__half*>(OUT2) + (long long)row * 128 + (cg - 128);
        *reinterpret_cast<uint2*>(dst) = u;
    }
}

// ---------------- K2: gammas, x_q, q, h0, h1 per query ----------------
__global__ __launch_bounds__(256) void k_feat(const float* __restrict__ x,
                                              const float* __restrict__ query_W,
                                              const float* __restrict__ query_b,
                                              const float* __restrict__ q_W,
                                              const float* __restrict__ band_W,
                                              const float* __restrict__ band_b) {
    __shared__ float sg[16][4];
    __shared__ float om0[8], om1[8];
    __shared__ float gq[16][64];
    __shared__ float g1s[16][64];
    __shared__ float xq[16][256];
    int tid = threadIdx.x;
    int q0 = blockIdx.x * 16;
    if (tid < 8) {
        const float stop0 = (float)2.1072099696478683;   // log10(128)
        float e0 = 1.0f + (float)tid * ((stop0 - 1.0f) / 7.0f);
        om0[tid] = (float)exp10((double)e0);
        const float stop1 = (float)1.5051499783199061;   // log10(32)
        float e1 = 1.0f + (float)tid * ((stop1 - 1.0f) / 7.0f);
        om1[tid] = (float)exp10((double)e1);
    }
    if (tid < 64) sg[tid >> 2][tid & 3] = x[(q0 + (tid >> 2)) * 4 + (tid & 3)];
    __syncthreads();
    for (int i = tid; i < 16 * 64; i += 256) {
        int r = i >> 6, f = i & 63;
        int d = f >> 4, j = f & 15;
        float pg = (float)M_PI * sg[r][d];
        int jj = (j < 8) ? j : j - 8;
        float a0 = pg * om0[jj];
        float a1 = pg * om1[jj];
        gq[r][f]  = (j < 8) ? sinf(a0) : cosf(a0);
        g1s[r][f] = (j < 8) ? sinf(a1) : cosf(a1);
    }
    __syncthreads();
    float accx[16], acc0[16], acc1[16];
#pragma unroll
    for (int r = 0; r < 16; r++) { accx[r] = 0.f; acc0[r] = 0.f; acc1[r] = 0.f; }
    for (int f = 0; f < 64; f++) {
        float wq = query_W[f * 256 + tid];
        float w0 = band_W[f * 256 + tid];
        float w1 = band_W[64 * 256 + f * 256 + tid];
#pragma unroll
        for (int r = 0; r < 16; r++) {
            float gv = gq[r][f];
            accx[r] = fmaf(gv, wq, accx[r]);
            acc0[r] = fmaf(gv, w0, acc0[r]);
            acc1[r] = fmaf(g1s[r][f], w1, acc1[r]);
        }
    }
    float qb = query_b[tid], b0 = band_b[tid], b1 = band_b[256 + tid];
#pragma unroll
    for (int r = 0; r < 16; r++) {
        float xv = fmaxf(accx[r] + qb, 0.f);
        xq[r][tid] = xv;
        g_h0[(q0 + r) * 256 + tid] = fmaxf(acc0[r] + b0, 0.f);
        g_h1[(q0 + r) * 256 + tid] = fmaxf(acc1[r] + b1, 0.f);
    }
    __syncthreads();
    int c  = tid & 127;
    int rh = tid >> 7;
    float accq[8];
#pragma unroll
    for (int r = 0; r < 8; r++) accq[r] = 0.f;
    for (int h = 0; h < 256; h++) {
        float w = q_W[h * 128 + c];
#pragma unroll
        for (int r = 0; r < 8; r++) accq[r] = fmaf(xq[rh * 8 + r][h], w, accq[r]);
    }
#pragma unroll
    for (int r = 0; r < 8; r++) g_q[(q0 + rh * 8 + r) * 128 + c] = accq[r];
}

// ---------------- K3: windowed sparse attention, block per (q, b) -------
__global__ __launch_bounds__(256) void k_attn(const float* __restrict__ x,
                                              const int* gDp, const int* gHp,
                                              const int* gWp, const int* gTp) {
    __shared__ __align__(16) float qs[128];
    __shared__ float ps[2][128];
    __shared__ float dnm[2];
    __shared__ __align__(16) float op[16][128];
    int tid = threadIdx.x;
    int q = blockIdx.x >> 1;
    int b = blockIdx.x & 1;
    if (tid < 128) qs[tid] = g_q[q * 128 + tid];

    int gD = *gDp, gH = *gHp, gW = *gWp, gT = *gTp;
    float x0 = x[q * 4 + 0], x1 = x[q * 4 + 1], x2 = x[q * 4 + 2], x3 = x[q * 4 + 3];
    int zi = (int)(x0 * (float)gD);
    int yi = (int)(x1 * (float)gH);
    int xi = (int)(x2 * (float)gW);
    int ti = (int)(x3 * (float)gT);
    int idx = ((ti * gD + zi) * gH + yi) * gW + xi;
    long long Ntot = (long long)gD * gH * gW * gT;
    long long a2 = 2LL * idx * LN;
    long long num = a2 - Ntot, den = 2LL * Ntot;
    long long cl = (num >= 0) ? (num + den - 1) / den : -((-num) / den);  // ceil
    int s = (int)cl - 64;
    if (s < 0) s = 0;
    if (s > LN - TOPK) s = LN - TOPK;
    __syncthreads();

    int lane = tid & 31;
    int warp = tid >> 5;

    // sim: each warp 16 keys, 2 keys per iteration (LDG.128 per lane)
    {
        const __half* kb = g_kh + b * LN * 128;
        int halfp = lane >> 4;
        int l16 = lane & 15;
        float qv[8];
        {
            float4 q0 = *reinterpret_cast<const float4*>(qs + l16 * 8);
            float4 q1 = *reinterpret_cast<const float4*>(qs + l16 * 8 + 4);
            qv[0] = q0.x; qv[1] = q0.y; qv[2] = q0.z; qv[3] = q0.w;
            qv[4] = q1.x; qv[5] = q1.y; qv[6] = q1.z; qv[7] = q1.w;
        }
#pragma unroll
        for (int it = 0; it < 8; it++) {
            int k = warp * 16 + it * 2 + halfp;
            uint4 raw = *reinterpret_cast<const uint4*>(kb + (s + k) * 128 + l16 * 8);
            __half2 h0 = *reinterpret_cast<__half2*>(&raw.x);
            __half2 h1 = *reinterpret_cast<__half2*>(&raw.y);
            __half2 h2 = *reinterpret_cast<__half2*>(&raw.z);
            __half2 h3 = *reinterpret_cast<__half2*>(&raw.w);
            float2 f0 = __half22float2(h0);
            float2 f1 = __half22float2(h1);
            float2 f2 = __half22float2(h2);
            float2 f3 = __half22float2(h3);
            float part = f0.x * qv[0] + f0.y * qv[1] + f1.x * qv[2] + f1.y * qv[3]
                       + f2.x * qv[4] + f2.y * qv[5] + f3.x * qv[6] + f3.y * qv[7];
            part += __shfl_xor_sync(0xffffffffu, part, 1);
            part += __shfl_xor_sync(0xffffffffu, part, 2);
            part += __shfl_xor_sync(0xffffffffu, part, 4);
            if ((lane & 7) == 0) ps[(lane >> 3) & 1][k] = part * 0.125f;
        }
    }
    __syncthreads();
    if (tid < 64) {
        int h = warp;
        float v[4];
        float mx = -3.4e38f;
#pragma unroll
        for (int j2 = 0; j2 < 4; j2++) { v[j2] = ps[h][lane + 32 * j2]; mx = fmaxf(mx, v[j2]); }
#pragma unroll
        for (int o2 = 16; o2 > 0; o2 >>= 1) mx = fmaxf(mx, __shfl_xor_sync(0xffffffffu, mx, o2));
        float sum = 0.f;
#pragma unroll
        for (int j2 = 0; j2 < 4; j2++) {
            float ev = expf(v[j2] - mx);
            ps[h][lane + 32 * j2] = ev;
            sum += ev;
        }
#pragma unroll
        for (int o2 = 16; o2 > 0; o2 >>= 1) sum += __shfl_xor_sync(0xffffffffu, sum, o2);
        if (lane == 0) dnm[h] = sum;
    }
    __syncthreads();
    {
        int j8 = (tid & 15) * 8;
        int kg = tid >> 4;
        int h = j8 >> 6;
        const __half* vb = g_vh + b * LN * 128;
        float a[8];
#pragma unroll
        for (int i = 0; i < 8; i++) a[i] = 0.f;
#pragma unroll
        for (int kk = 0; kk < 8; kk++) {
            int k = kg * 8 + kk;
            float p = ps[h][k];
            uint4 raw = *reinterpret_cast<const uint4*>(vb + (s + k) * 128 + j8);
            __half2 h0 = *reinterpret_cast<__half2*>(&raw.x);
            __half2 h1 = *reinterpret_cast<__half2*>(&raw.y);
            __half2 h2 = *reinterpret_cast<__half2*>(&raw.z);
            __half2 h3 = *reinterpret_cast<__half2*>(&raw.w);
            float2 f0 = __half22float2(h0);
            float2 f1 = __half22float2(h1);
            float2 f2 = __half22float2(h2);
            float2 f3 = __half22float2(h3);
            a[0] = fmaf(p, f0.x, a[0]); a[1] = fmaf(p, f0.y, a[1]);
            a[2] = fmaf(p, f1.x, a[2]); a[3] = fmaf(p, f1.y, a[3]);
            a[4] = fmaf(p, f2.x, a[4]); a[5] = fmaf(p, f2.y, a[5]);
            a[6] = fmaf(p, f3.x, a[6]); a[7] = fmaf(p, f3.y, a[7]);
        }
        *reinterpret_cast<float4*>(&op[kg][j8])     = make_float4(a[0], a[1], a[2], a[3]);
        *reinterpret_cast<float4*>(&op[kg][j8 + 4]) = make_float4(a[4], a[5], a[6], a[7]);
    }
    __syncthreads();
    if (tid < 128) {
        float v = 0.f;
#pragma unroll
        for (int g = 0; g < 16; g++) v += op[g][tid];
        g_o[((long long)b * QN + q) * 128 + tid] = v / dnm[tid >> 6];
    }
}

// ---------------- K7: out = m0 . outlW0 + hv1 . outlW1 + biases ---------
__global__ __launch_bounds__(256) void k_out(const float* __restrict__ outl_W,
                                             const float* __restrict__ outl_b,
                                             float* __restrict__ out) {
    int tid = threadIdx.x;
    int r = blockIdx.x * 8 + (tid >> 5);
    int lane = tid & 31;
    float acc = 0.f;
#pragma unroll
    for (int j = 0; j < 8; j++) {
        int c = lane + 32 * j;
        acc = fmaf(g_m0[(long long)r * 256 + c],  outl_W[c],       acc);
        acc = fmaf(g_hv1[(long long)r * 256 + c], outl_W[256 + c], acc);
    }
#pragma unroll
    for (int o2 = 16; o2 > 0; o2 >>= 1) acc += __shfl_xor_sync(0xffffffffu, acc, o2);
    if (lane == 0) out[r] = acc + outl_b[0] + outl_b[1];
}

// ---------------- launch ------------------------------------------------
extern "C" void kernel_launch(void* const* d_in, const int* in_sizes, int n_in,
                              void* d_out, int out_size) {
    const float* x       = (const float*)d_in[0];
    const float* tokens  = (const float*)d_in[1];
    const float* query_W = (const float*)d_in[2];
    const float* query_b = (const float*)d_in[3];
    const float* q_W     = (const float*)d_in[4];
    const float* kv_W    = (const float*)d_in[5];
    const float* out_W   = (const float*)d_in[6];
    const float* out_b   = (const float*)d_in[7];
    const float* band_W  = (const float*)d_in[8];
    const float* band_b  = (const float*)d_in[9];
    const float* mod_W   = (const float*)d_in[10];
    const float* mod_b   = (const float*)d_in[11];
    const float* hv_W    = (const float*)d_in[12];
    const float* hv_b    = (const float*)d_in[13];
    const float* outl_W  = (const float*)d_in[14];
    const float* outl_b  = (const float*)d_in[15];
    const int*   gD      = (const int*)d_in[16];
    const int*   gH      = (const int*)d_in[17];
    const int*   gW      = (const int*)d_in[18];
    const int*   gT      = (const int*)d_in[19];
    float* out = (float*)d_out;

    float *o, *mod, *m0, *m1, *hv1, *h0, *h1;
    __half *kf, *vf, *wh, *wl;
    cudaGetSymbolAddress((void**)&kf,  g_kh);
    cudaGetSymbolAddress((void**)&vf,  g_vh);
    cudaGetSymbolAddress((void**)&o,   g_o);
    cudaGetSymbolAddress((void**)&mod, g_mod);
    cudaGetSymbolAddress((void**)&m0,  g_m0);
    cudaGetSymbolAddress((void**)&m1,  g_m1);
    cudaGetSymbolAddress((void**)&hv1, g_hv1);
    cudaGetSymbolAddress((void**)&h0,  g_h0);
    cudaGetSymbolAddress((void**)&h1,  g_h1);
    cudaGetSymbolAddress((void**)&wh,  g_wh);
    cudaGetSymbolAddress((void**)&wl,  g_wl);

    k_wprep<<<229376 / 256, 256>>>(out_W, mod_W, hv_W);
    k_gemm<256,32,0><<<(BN*LN/32)*2, 256>>>(tokens, nullptr, kv_W, nullptr, nullptr, (float*)kf, (float*)vf);
    k_feat<<<QN/16, 256>>>(x, query_W, query_b, q_W, band_W, band_b);
    k_attn<<<BN*QN, 256>>>(x, gD, gH, gW, gT);
    k_tmma<128,1><<<(BN*QN/64)*2, 256>>>(o,   nullptr, wh,          wl,          out_b,       nullptr, mod);
    k_tmma<256,2><<<(BN*QN/64)*2, 256>>>(mod, nullptr, wh + 32768,  wl + 32768,  mod_b,       h0,      m0);
    k_tmma<256,2><<<(BN*QN/64)*2, 256>>>(mod, nullptr, wh + 98304,  wl + 98304,  mod_b + 256, h1,      m1);
    k_tmma<256,3><<<(BN*QN/64)*2, 256>>>(m0,  m1,      wh + 163840, wl + 163840, hv_b,        nullptr, hv1);
    k_out<<<BN*QN/8, 256>>>(outl_W, outl_b, out);
}

// round 16
// speedup vs baseline: 1.5979x; 1.0257x over previous
#include <cuda_runtime.h>
#include <cuda_fp16.h>
#include <math.h>
#include <stdint.h>

#define QN 4096
#define LN 1024
#define BN 2
#define TOPK 128

// ---------------- scratch (device globals; no allocation) ----------------
__device__ __half g_kh[BN*LN*128];
__device__ __half g_vh[BN*LN*128];
__device__ float g_q[QN*128];
__device__ float g_h0[QN*256];
__device__ float g_h1[QN*256];
__device__ float g_o[BN*QN*128];
__device__ float g_mod[BN*QN*256];
__device__ float g_m0[BN*QN*256];
__device__ float g_m1[BN*QN*256];
__device__ float g_hv1[BN*QN*256];
// transposed hi/lo split weights [n][k], slots:
//  s0 out_W  [256][128] @0 ; s1 mod_W0 [256][256] @32768
//  s2 mod_W1 [256][256] @98304 ; s3 hv_W [256][256] @163840
__device__ __half g_wh[229376];
__device__ __half g_wl[229376];

// ---------------- combined weight prep: transpose + fp16 hi/lo ----------
__global__ __launch_bounds__(256) void k_wprep(const float* __restrict__ out_W,
                                               const float* __restrict__ mod_W,
                                               const float* __restrict__ hv_W) {
    int e = blockIdx.x * 256 + threadIdx.x;   // 0 .. 229375
    const float* W; int base, K, N, off;
    if (e < 32768)       { W = out_W;          base = 0;      K = 128; N = 256; off = e; }
    else if (e < 98304)  { W = mod_W;          base = 32768;  K = 256; N = 256; off = e - 32768; }
    else if (e < 163840) { W = mod_W + 65536;  base = 98304;  K = 256; N = 256; off = e - 98304; }
    else                 { W = hv_W;           base = 163840; K = 256; N = 256; off = e - 163840; }
    int k = off / N, n = off % N;             // src is [K][N] row-major
    float w = W[off];
    __half hi = __float2half_rn(w);
    float lo = w - __half2float(hi);
    g_wh[base + n * K + k] = hi;
    g_wl[base + n * K + k] = __float2half_rn(lo);
}

// ---------------- mma / ldmatrix helpers --------------------------------
__device__ __forceinline__ void mma16816(float* c, const uint32_t* a, const uint32_t b0,
                                         const uint32_t b1) {
    asm("mma.sync.aligned.m16n8k16.row.col.f32.f16.f16.f32 "
        "{%0,%1,%2,%3}, {%4,%5,%6,%7}, {%8,%9}, {%0,%1,%2,%3};"
        : "+f"(c[0]), "+f"(c[1]), "+f"(c[2]), "+f"(c[3])
        : "r"(a[0]), "r"(a[1]), "r"(a[2]), "r"(a[3]), "r"(b0), "r"(b1));
}
__device__ __forceinline__ void ldsm4(uint32_t* r, const __half* p) {
    uint32_t addr = (uint32_t)__cvta_generic_to_shared(p);
    asm volatile("ldmatrix.sync.aligned.m8n8.x4.shared.b16 {%0,%1,%2,%3}, [%4];"
                 : "=r"(r[0]), "=r"(r[1]), "=r"(r[2]), "=r"(r[3]) : "r"(addr));
}

// ---------------- tensor-core GEMM: OUT[8192 x 256] = X @ W + ... -------
// Block 64 rows x 128 cols, 8 warps (warp: 32x32 tile). fp16 hi/lo 3-term.
// Fragments loaded via ldmatrix.x4 (conflict-free at P=40 pitch).
// MODE 1: OUT = X@W + b ; MODE 2: relu(hadd[row&4095] + X@W + b)
// MODE 3: relu((X+X2)@W + b)
template<int KDIM, int MODE>
__global__ __launch_bounds__(256) void k_tmma(const float* __restrict__ X,
                                              const float* __restrict__ X2,
                                              const __half* __restrict__ Wh,
                                              const __half* __restrict__ Wl,
                                              const float* __restrict__ bias,
                                              const float* __restrict__ hadd,
                                              float* __restrict__ OUT) {
    const int P = 40;                         // padded halves per 32-k row
    __shared__ __half Ah[64 * P], Al[64 * P];
    __shared__ __half Bh[128 * P], Bl[128 * P];
    int tid = threadIdx.x, lane = tid & 31, warp = tid >> 5;
    int nb = blockIdx.x & 1;
    int r0 = (blockIdx.x >> 1) * 64;
    int n0 = nb * 128;
    int wm = (warp & 1) * 32;                 // warp row offset in block
    int wn = (warp >> 1) * 32;                // warp col offset in 128
    int g = lane >> 2, tig = lane & 3;
    int lr = lane & 15, lk = (lane >> 4) * 8; // ldmatrix row / k-offset

    float acc[2][4][4];
#pragma unroll
    for (int m = 0; m < 2; m++)
#pragma unroll
        for (int n = 0; n < 4; n++)
#pragma unroll
            for (int j = 0; j < 4; j++) acc[m][n][j] = 0.f;

    for (int kc = 0; kc < KDIM; kc += 32) {
        // stage A: 64 rows x 32 k fp32 -> hi/lo fp16
#pragma unroll
        for (int it = 0; it < 2; it++) {
            int i = it * 256 + tid;
            int row = i >> 3, k4 = (i & 7) * 4;
            float4 v = *reinterpret_cast<const float4*>(
                X + (long long)(r0 + row) * KDIM + kc + k4);
            if (MODE == 3) {
                float4 v2 = *reinterpret_cast<const float4*>(
                    X2 + (long long)(r0 + row) * KDIM + kc + k4);
                v.x += v2.x; v.y += v2.y; v.z += v2.z; v.w += v2.w;
            }
            __half hx = __float2half_rn(v.x), hy = __float2half_rn(v.y);
            __half hz = __float2half_rn(v.z), hw = __float2half_rn(v.w);
            __half2 h01; h01.x = hx; h01.y = hy;
            __half2 h23; h23.x = hz; h23.y = hw;
            uint2 uh;
            uh.x = *reinterpret_cast<unsigned*>(&h01);
            uh.y = *reinterpret_cast<unsigned*>(&h23);
            *reinterpret_cast<uint2*>(&Ah[row * P + k4]) = uh;
            __half2 l01 = __floats2half2_rn(v.x - __half2float(hx), v.y - __half2float(hy));
            __half2 l23 = __floats2half2_rn(v.z - __half2float(hz), v.w - __half2float(hw));
            uint2 ul;
            ul.x = *reinterpret_cast<unsigned*>(&l01);
            ul.y = *reinterpret_cast<unsigned*>(&l23);
            *reinterpret_cast<uint2*>(&Al[row * P + k4]) = ul;
        }
        // stage B: Wh/Wl [n][KDIM] rows n0..n0+127, k kc..kc+31
#pragma unroll
        for (int it = 0; it < 2; it++) {
            int i = it * 256 + tid;
            int n = i >> 2, k8 = (i & 3) * 8;
            uint4 h = *reinterpret_cast<const uint4*>(Wh + (long long)(n0 + n) * KDIM + kc + k8);
            *reinterpret_cast<uint4*>(&Bh[n * P + k8]) = h;
            uint4 l = *reinterpret_cast<const uint4*>(Wl + (long long)(n0 + n) * KDIM + kc + k8);
            *reinterpret_cast<uint4*>(&Bl[n * P + k8]) = l;
        }
        __syncthreads();
#pragma unroll
        for (int ks = 0; ks < 32; ks += 16) {
            uint32_t ah[2][4], al[2][4], bh[2][4], bl[2][4];
#pragma unroll
            for (int m = 0; m < 2; m++) {
                int rb = wm + m * 16;
                ldsm4(ah[m], &Ah[(rb + lr) * P + ks + lk]);
                ldsm4(al[m], &Al[(rb + lr) * P + ks + lk]);
            }
#pragma unroll
            for (int gN = 0; gN < 2; gN++) {
                int bn = wn + gN * 16;
                ldsm4(bh[gN], &Bh[(bn + lr) * P + ks + lk]);
                ldsm4(bl[gN], &Bl[(bn + lr) * P + ks + lk]);
            }
#pragma unroll
            for (int m = 0; m < 2; m++)
#pragma unroll
                for (int n = 0; n < 4; n++) {
                    int gN = n >> 1, c = n & 1;
                    mma16816(acc[m][n], ah[m], bh[gN][c], bh[gN][c + 2]);
                    mma16816(acc[m][n], ah[m], bl[gN][c], bl[gN][c + 2]);
                    mma16816(acc[m][n], al[m], bh[gN][c], bh[gN][c + 2]);
                }
        }
        __syncthreads();
    }

    // epilogue: c0,c1 = (row g, col 2tig..+1); c2,c3 = (row g+8, same cols)
#pragma unroll
    for (int m = 0; m < 2; m++)
#pragma unroll
        for (int n = 0; n < 4; n++) {
            int row = r0 + wm + m * 16 + g;
            int col = n0 + wn + n * 8 + 2 * tig;
            float2 bv = *reinterpret_cast<const float2*>(bias + col);
            float v0 = acc[m][n][0] + bv.x, v1 = acc[m][n][1] + bv.y;
            float v2 = acc[m][n][2] + bv.x, v3 = acc[m][n][3] + bv.y;
            if (MODE == 2) {
                float2 h0 = *reinterpret_cast<const float2*>(
                    hadd + (long long)(row & (QN - 1)) * 256 + col);
                float2 h1 = *reinterpret_cast<const float2*>(
                    hadd + (long long)((row + 8) & (QN - 1)) * 256 + col);
                v0 += h0.x; v1 += h0.y; v2 += h1.x; v3 += h1.y;
            }
            if (MODE >= 2) {
                v0 = fmaxf(v0, 0.f); v1 = fmaxf(v1, 0.f);
                v2 = fmaxf(v2, 0.f); v3 = fmaxf(v3, 0.f);
            }
            *reinterpret_cast<float2*>(OUT + (long long)row * 256 + col) = make_float2(v0, v1);
            *reinterpret_cast<float2*>(OUT + (long long)(row + 8) * 256 + col) = make_float2(v2, v3);
        }
}

// ------- scalar double-buffered GEMM (kv only, MODE 0) ------------------
template<int KDIM, int ROWS, int MODE>
__global__ __launch_bounds__(256) void k_gemm(const float* __restrict__ X,
                                              const float* __restrict__ X2,
                                              const float* __restrict__ W,
                                              const float* __restrict__ bias,
                                              const float* __restrict__ hadd,
                                              float* __restrict__ OUT,
                                              float* __restrict__ OUT2) {
    const int RPT = ROWS / 8;
    const int NCH = KDIM / 16;
    __shared__ float As[2][16][ROWS];
    __shared__ float Bs[2][16][128];
    int tid = threadIdx.x;
    int cb = blockIdx.x & 1;
    int r0 = (blockIdx.x >> 1) * ROWS;
    int ty = tid >> 5;
    int tx = tid & 31;
    int cg = cb * 128 + tx * 4;

    bool a_act; int a_row, a_kg;
    if (ROWS == 64) { a_act = true;      a_row = tid & 63; a_kg = tid >> 6; }
    else            { a_act = tid < 128; a_row = tid & 31; a_kg = tid >> 5; }
    int b_k = tid >> 4, b_c = (tid & 15) * 8;

    float acc[RPT][4];
#pragma unroll
    for (int r = 0; r < RPT; r++)
#pragma unroll
        for (int j = 0; j < 4; j++) acc[r][j] = 0.f;

    float4 apre = make_float4(0.f, 0.f, 0.f, 0.f);
    float4 bpre0, bpre1;
    if (a_act) {
        apre = *reinterpret_cast<const float4*>(
            X + (long long)(r0 + a_row) * KDIM + a_kg * 4);
    }
    bpre0 = *reinterpret_cast<const float4*>(W + (long long)b_k * 256 + cb * 128 + b_c);
    bpre1 = *reinterpret_cast<const float4*>(W + (long long)b_k * 256 + cb * 128 + b_c + 4);

    for (int c = 0; c < NCH; c++) {
        int buf = c & 1;
        if (a_act) {
            As[buf][a_kg * 4 + 0][a_row] = apre.x;
            As[buf][a_kg * 4 + 1][a_row] = apre.y;
            As[buf][a_kg * 4 + 2][a_row] = apre.z;
            As[buf][a_kg * 4 + 3][a_row] = apre.w;
        }
        *reinterpret_cast<float4*>(&Bs[buf][b_k][b_c])     = bpre0;
        *reinterpret_cast<float4*>(&Bs[buf][b_k][b_c + 4]) = bpre1;
        __syncthreads();
        if (c + 1 < NCH) {
            int kc = (c + 1) * 16;
            if (a_act) {
                apre = *reinterpret_cast<const float4*>(
                    X + (long long)(r0 + a_row) * KDIM + kc + a_kg * 4);
            }
            bpre0 = *reinterpret_cast<const float4*>(
                W + (long long)(kc + b_k) * 256 + cb * 128 + b_c);
            bpre1 = *reinterpret_cast<const float4*>(
                W + (long long)(kc + b_k) * 256 + cb * 128 + b_c + 4);
        }
#pragma unroll
        for (int k = 0; k < 16; k++) {
            float4 b4 = *reinterpret_cast<const float4*>(&Bs[buf][k][tx * 4]);
            float ar[RPT];
            float4 t0 = *reinterpret_cast<const float4*>(&As[buf][k][ty * RPT]);
            ar[0] = t0.x; ar[1] = t0.y; ar[2] = t0.z; ar[3] = t0.w;
#pragma unroll
            for (int r = 0; r < RPT; r++) {
                acc[r][0] = fmaf(ar[r], b4.x, acc[r][0]);
                acc[r][1] = fmaf(ar[r], b4.y, acc[r][1]);
                acc[r][2] = fmaf(ar[r], b4.z, acc[r][2]);
                acc[r][3] = fmaf(ar[r], b4.w, acc[r][3]);
            }
        }
        __syncthreads();
    }

#pragma unroll
    for (int r = 0; r < RPT; r++) {
        int row = r0 + ty * RPT + r;
        float4 v;
        v.x = acc[r][0]; v.y = acc[r][1]; v.z = acc[r][2]; v.w = acc[r][3];
        __half2 p0 = __floats2half2_rn(v.x, v.y);
        __half2 p1 = __floats2half2_rn(v.z, v.w);
        uint2 u;
        u.x = *reinterpret_cast<unsigned*>(&p0);
        u.y = *reinterpret_cast<unsigned*>(&p1);
        __half* dst = (cb == 0)
            ? reinterpret_cast<__half*>(OUT)  + (long long)row * 128 + cg
            : reinterpret_cast<__half*>(OUT2) + (long long)row * 128 + (cg - 128);
        *reinterpret_cast<uint2*>(dst) = u;
    }
}

// ---------------- K2: gammas, x_q, q, h0, h1 per query ----------------
__global__ __launch_bounds__(256) void k_feat(const float* __restrict__ x,
                                              const float* __restrict__ query_W,
                                              const float* __restrict__ query_b,
                                              const float* __restrict__ q_W,
                                              const float* __restrict__ band_W,
                                              const float* __restrict__ band_b) {
    __shared__ float sg[16][4];
    __shared__ float om0[8], om1[8];
    __shared__ float gq[16][64];
    __shared__ float g1s[16][64];
    __shared__ float xq[16][256];
    int tid = threadIdx.x;
    int q0 = blockIdx.x * 16;
    if (tid < 8) {
        const float stop0 = (float)2.1072099696478683;   // log10(128)
        float e0 = 1.0f + (float)tid * ((stop0 - 1.0f) / 7.0f);
        om0[tid] = (float)exp10((double)e0);
        const float stop1 = (float)1.5051499783199061;   // log10(32)
        float e1 = 1.0f + (float)tid * ((stop1 - 1.0f) / 7.0f);
        om1[tid] = (float)exp10((double)e1);
    }
    if (tid < 64) sg[tid >> 2][tid & 3] = x[(q0 + (tid >> 2)) * 4 + (tid & 3)];
    __syncthreads();
    for (int i = tid; i < 16 * 64; i += 256) {
        int r = i >> 6, f = i & 63;
        int d = f >> 4, j = f & 15;
        float pg = (float)M_PI * sg[r][d];
        int jj = (j < 8) ? j : j - 8;
        float a0 = pg * om0[jj];
        float a1 = pg * om1[jj];
        gq[r][f]  = (j < 8) ? sinf(a0) : cosf(a0);
        g1s[r][f] = (j < 8) ? sinf(a1) : cosf(a1);
    }
    __syncthreads();
    float accx[16], acc0[16], acc1[16];
#pragma unroll
    for (int r = 0; r < 16; r++) { accx[r] = 0.f; acc0[r] = 0.f; acc1[r] = 0.f; }
    for (int f = 0; f < 64; f++) {
        float wq = query_W[f * 256 + tid];
        float w0 = band_W[f * 256 + tid];
        float w1 = band_W[64 * 256 + f * 256 + tid];
#pragma unroll
        for (int r = 0; r < 16; r++) {
            float gv = gq[r][f];
            accx[r] = fmaf(gv, wq, accx[r]);
            acc0[r] = fmaf(gv, w0, acc0[r]);
            acc1[r] = fmaf(g1s[r][f], w1, acc1[r]);
        }
    }
    float qb = query_b[tid], b0 = band_b[tid], b1 = band_b[256 + tid];
#pragma unroll
    for (int r = 0; r < 16; r++) {
        float xv = fmaxf(accx[r] + qb, 0.f);
        xq[r][tid] = xv;
        g_h0[(q0 + r) * 256 + tid] = fmaxf(acc0[r] + b0, 0.f);
        g_h1[(q0 + r) * 256 + tid] = fmaxf(acc1[r] + b1, 0.f);
    }
    __syncthreads();
    int c  = tid & 127;
    int rh = tid >> 7;
    float accq[8];
#pragma unroll
    for (int r = 0; r < 8; r++) accq[r] = 0.f;
    for (int h = 0; h < 256; h++) {
        float w = q_W[h * 128 + c];
#pragma unroll
        for (int r = 0; r < 8; r++) accq[r] = fmaf(xq[rh * 8 + r][h], w, accq[r]);
    }
#pragma unroll
    for (int r = 0; r < 8; r++) g_q[(q0 + rh * 8 + r) * 128 + c] = accq[r];
}

// ---------------- K3: windowed sparse attention, block per (q, b) -------
__global__ __launch_bounds__(256) void k_attn(const float* __restrict__ x,
                                              const int* gDp, const int* gHp,
                                              const int* gWp, const int* gTp) {
    __shared__ __align__(16) float qs[128];
    __shared__ float ps[2][128];
    __shared__ float dnm[2];
    __shared__ __align__(16) float op[16][128];
    int tid = threadIdx.x;
    int q = blockIdx.x >> 1;
    int b = blockIdx.x & 1;
    if (tid < 128) qs[tid] = g_q[q * 128 + tid];

    int gD = *gDp, gH = *gHp, gW = *gWp, gT = *gTp;
    float x0 = x[q * 4 + 0], x1 = x[q * 4 + 1], x2 = x[q * 4 + 2], x3 = x[q * 4 + 3];
    int zi = (int)(x0 * (float)gD);
    int yi = (int)(x1 * (float)gH);
    int xi = (int)(x2 * (float)gW);
    int ti = (int)(x3 * (float)gT);
    int idx = ((ti * gD + zi) * gH + yi) * gW + xi;
    long long Ntot = (long long)gD * gH * gW * gT;
    long long a2 = 2LL * idx * LN;
    long long num = a2 - Ntot, den = 2LL * Ntot;
    long long cl = (num >= 0) ? (num + den - 1) / den : -((-num) / den);  // ceil
    int s = (int)cl - 64;
    if (s < 0) s = 0;
    if (s > LN - TOPK) s = LN - TOPK;
    __syncthreads();

    int lane = tid & 31;
    int warp = tid >> 5;

    // sim: each warp 16 keys, 2 keys per iteration (LDG.128 per lane)
    {
        const __half* kb = g_kh + b * LN * 128;
        int halfp = lane >> 4;
        int l16 = lane & 15;
        float qv[8];
        {
            float4 q0 = *reinterpret_cast<const float4*>(qs + l16 * 8);
            float4 q1 = *reinterpret_cast<const float4*>(qs + l16 * 8 + 4);
            qv[0] = q0.x; qv[1] = q0.y; qv[2] = q0.z; qv[3] = q0.w;
            qv[4] = q1.x; qv[5] = q1.y; qv[6] = q1.z; qv[7] = q1.w;
        }
#pragma unroll
        for (int it = 0; it < 8; it++) {
            int k = warp * 16 + it * 2 + halfp;
            uint4 raw = *reinterpret_cast<const uint4*>(kb + (s + k) * 128 + l16 * 8);
            __half2 h0 = *reinterpret_cast<__half2*>(&raw.x);
            __half2 h1 = *reinterpret_cast<__half2*>(&raw.y);
            __half2 h2 = *reinterpret_cast<__half2*>(&raw.z);
            __half2 h3 = *reinterpret_cast<__half2*>(&raw.w);
            float2 f0 = __half22float2(h0);
            float2 f1 = __half22float2(h1);
            float2 f2 = __half22float2(h2);
            float2 f3 = __half22float2(h3);
            float part = f0.x * qv[0] + f0.y * qv[1] + f1.x * qv[2] + f1.y * qv[3]
                       + f2.x * qv[4] + f2.y * qv[5] + f3.x * qv[6] + f3.y * qv[7];
            part += __shfl_xor_sync(0xffffffffu, part, 1);
            part += __shfl_xor_sync(0xffffffffu, part, 2);
            part += __shfl_xor_sync(0xffffffffu, part, 4);
            if ((lane & 7) == 0) ps[(lane >> 3) & 1][k] = part * 0.125f;
        }
    }
    __syncthreads();
    if (tid < 64) {
        int h = warp;
        float v[4];
        float mx = -3.4e38f;
#pragma unroll
        for (int j2 = 0; j2 < 4; j2++) { v[j2] = ps[h][lane + 32 * j2]; mx = fmaxf(mx, v[j2]); }
#pragma unroll
        for (int o2 = 16; o2 > 0; o2 >>= 1) mx = fmaxf(mx, __shfl_xor_sync(0xffffffffu, mx, o2));
        float sum = 0.f;
#pragma unroll
        for (int j2 = 0; j2 < 4; j2++) {
            float ev = expf(v[j2] - mx);
            ps[h][lane + 32 * j2] = ev;
            sum += ev;
        }
#pragma unroll
        for (int o2 = 16; o2 > 0; o2 >>= 1) sum += __shfl_xor_sync(0xffffffffu, sum, o2);
        if (lane == 0) dnm[h] = sum;
    }
    __syncthreads();
    {
        int j8 = (tid & 15) * 8;
        int kg = tid >> 4;
        int h = j8 >> 6;
        const __half* vb = g_vh + b * LN * 128;
        float a[8];
#pragma unroll
        for (int i = 0; i < 8; i++) a[i] = 0.f;
#pragma unroll
        for (int kk = 0; kk < 8; kk++) {
            int k = kg * 8 + kk;
            float p = ps[h][k];
            uint4 raw = *reinterpret_cast<const uint4*>(vb + (s + k) * 128 + j8);
            __half2 h0 = *reinterpret_cast<__half2*>(&raw.x);
            __half2 h1 = *reinterpret_cast<__half2*>(&raw.y);
            __half2 h2 = *reinterpret_cast<__half2*>(&raw.z);
            __half2 h3 = *reinterpret_cast<__half2*>(&raw.w);
            float2 f0 = __half22float2(h0);
            float2 f1 = __half22float2(h1);
            float2 f2 = __half22float2(h2);
            float2 f3 = __half22float2(h3);
            a[0] = fmaf(p, f0.x, a[0]); a[1] = fmaf(p, f0.y, a[1]);
            a[2] = fmaf(p, f1.x, a[2]); a[3] = fmaf(p, f1.y, a[3]);
            a[4] = fmaf(p, f2.x, a[4]); a[5] = fmaf(p, f2.y, a[5]);
            a[6] = fmaf(p, f3.x, a[6]); a[7] = fmaf(p, f3.y, a[7]);
        }
        *reinterpret_cast<float4*>(&op[kg][j8])     = make_float4(a[0], a[1], a[2], a[3]);
        *reinterpret_cast<float4*>(&op[kg][j8 + 4]) = make_float4(a[4], a[5], a[6], a[7]);
    }
    __syncthreads();
    if (tid < 128) {
        float v = 0.f;
#pragma unroll
        for (int g = 0; g < 16; g++) v += op[g][tid];
        g_o[((long long)b * QN + q) * 128 + tid] = v / dnm[tid >> 6];
    }
}

// ---------------- K7: out = m0 . outlW0 + hv1 . outlW1 + biases ---------
__global__ __launch_bounds__(256) void k_out(const float* __restrict__ outl_W,
                                             const float* __restrict__ outl_b,
                                             float* __restrict__ out) {
    int tid = threadIdx.x;
    int r = blockIdx.x * 8 + (tid >> 5);
    int lane = tid & 31;
    float acc = 0.f;
#pragma unroll
    for (int j = 0; j < 8; j++) {
        int c = lane + 32 * j;
        acc = fmaf(g_m0[(long long)r * 256 + c],  outl_W[c],       acc);
        acc = fmaf(g_hv1[(long long)r * 256 + c], outl_W[256 + c], acc);
    }
#pragma unroll
    for (int o2 = 16; o2 > 0; o2 >>= 1) acc += __shfl_xor_sync(0xffffffffu, acc, o2);
    if (lane == 0) out[r] = acc + outl_b[0] + outl_b[1];
}

// ---------------- launch ------------------------------------------------
extern "C" void kernel_launch(void* const* d_in, const int* in_sizes, int n_in,
                              void* d_out, int out_size) {
    const float* x       = (const float*)d_in[0];
    const float* tokens  = (const float*)d_in[1];
    const float* query_W = (const float*)d_in[2];
    const float* query_b = (const float*)d_in[3];
    const float* q_W     = (const float*)d_in[4];
    const float* kv_W    = (const float*)d_in[5];
    const float* out_W   = (const float*)d_in[6];
    const float* out_b   = (const float*)d_in[7];
    const float* band_W  = (const float*)d_in[8];
    const float* band_b  = (const float*)d_in[9];
    const float* mod_W   = (const float*)d_in[10];
    const float* mod_b   = (const float*)d_in[11];
    const float* hv_W    = (const float*)d_in[12];
    const float* hv_b    = (const float*)d_in[13];
    const float* outl_W  = (const float*)d_in[14];
    const float* outl_b  = (const float*)d_in[15];
    const int*   gD      = (const int*)d_in[16];
    const int*   gH      = (const int*)d_in[17];
    const int*   gW      = (const int*)d_in[18];
    const int*   gT      = (const int*)d_in[19];
    float* out = (float*)d_out;

    float *o, *mod, *m0, *m1, *hv1, *h0, *h1;
    __half *kf, *vf, *wh, *wl;
    cudaGetSymbolAddress((void**)&kf,  g_kh);
    cudaGetSymbolAddress((void**)&vf,  g_vh);
    cudaGetSymbolAddress((void**)&o,   g_o);
    cudaGetSymbolAddress((void**)&mod, g_mod);
    cudaGetSymbolAddress((void**)&m0,  g_m0);
    cudaGetSymbolAddress((void**)&m1,  g_m1);
    cudaGetSymbolAddress((void**)&hv1, g_hv1);
    cudaGetSymbolAddress((void**)&h0,  g_h0);
    cudaGetSymbolAddress((void**)&h1,  g_h1);
    cudaGetSymbolAddress((void**)&wh,  g_wh);
    cudaGetSymbolAddress((void**)&wl,  g_wl);

    k_wprep<<<229376 / 256, 256>>>(out_W, mod_W, hv_W);
    k_gemm<256,32,0><<<(BN*LN/32)*2, 256>>>(tokens, nullptr, kv_W, nullptr, nullptr, (float*)kf, (float*)vf);
    k_feat<<<QN/16, 256>>>(x, query_W, query_b, q_W, band_W, band_b);
    k_attn<<<BN*QN, 256>>>(x, gD, gH, gW, gT);
    k_tmma<128,1><<<(BN*QN/64)*2, 256>>>(o,   nullptr, wh,          wl,          out_b,       nullptr, mod);
    k_tmma<256,2><<<(BN*QN/64)*2, 256>>>(mod, nullptr, wh + 32768,  wl + 32768,  mod_b,       h0,      m0);
    k_tmma<256,2><<<(BN*QN/64)*2, 256>>>(mod, nullptr, wh + 98304,  wl + 98304,  mod_b + 256, h1,      m1);
    k_tmma<256,3><<<(BN*QN/64)*2, 256>>>(m0,  m1,      wh + 163840, wl + 163840, hv_b,        nullptr, hv1);
    k_out<<<BN*QN/8, 256>>>(outl_W, outl_b, out);
}